// round 1
// baseline (speedup 1.0000x reference)
#include <cuda_runtime.h>

#define DD 1024
#define BB 64
#define BETA_W 0.001f

__global__ __launch_bounds__(1024) void oscarmax_kernel(const float* __restrict__ x,
                                                        float* __restrict__ out) {
    __shared__ float key[DD];     // sort keys (|x| desc), later reused
    __shared__ int   perm[DD];    // argsort payload
    __shared__ float sx[DD];      // original x (for sign)
    __shared__ float yv[DD];      // s values -> isotonic y
    __shared__ float zbuf[DD];    // unsorted z (oscar prox output)
    __shared__ float zs[DD];      // z sorted desc (sparsemax)
    __shared__ float st_sum[DD];  // PAVA stack sums, reused as scan buffer
    __shared__ int   st_cnt[DD];  // PAVA stack counts
    __shared__ float tau_sh;

    const int tid = threadIdx.x;
    const int row = blockIdx.x;

    // ---- load row ----
    float xv = x[row * DD + tid];
    sx[tid]  = xv;
    key[tid] = fabsf(xv);
    perm[tid] = tid;
    __syncthreads();

    // ---- bitonic sort: key descending, carry perm ----
    #pragma unroll 1
    for (int k = 2; k <= DD; k <<= 1) {
        #pragma unroll 1
        for (int j = k >> 1; j > 0; j >>= 1) {
            int ixj = tid ^ j;
            if (ixj > tid) {
                bool dec = ((tid & k) == 0);   // descending sub-run
                float a = key[tid], b = key[ixj];
                if ((a < b) == dec) {
                    key[tid] = b; key[ixj] = a;
                    int pa = perm[tid]; perm[tid] = perm[ixj]; perm[ixj] = pa;
                }
            }
            __syncthreads();
        }
    }

    // ---- s_i = a_sorted_i - BETA*(D-1-i) ----
    yv[tid] = key[tid] - BETA_W * (float)(DD - 1 - tid);
    __syncthreads();

    // ---- PAVA (nonincreasing isotonic regression), serial on thread 0 ----
    if (tid == 0) {
        int sp = 0;
        float top_sum = yv[0];
        float top_cnt = 1.0f;
        for (int i = 1; i < DD; i++) {
            float cs = yv[i];
            float cc = 1.0f;
            // violation: cur_mean > top_mean  (counts positive -> cross-multiply)
            while (cs * top_cnt > top_sum * cc) {
                cs += top_sum; cc += top_cnt;
                if (sp > 0) { --sp; top_sum = st_sum[sp]; top_cnt = (float)st_cnt[sp]; }
                else        { top_cnt = 0.0f; break; }
            }
            if (top_cnt > 0.0f) { st_sum[sp] = top_sum; st_cnt[sp] = (int)top_cnt; sp++; }
            top_sum = cs; top_cnt = cc;
        }
        st_sum[sp] = top_sum; st_cnt[sp] = (int)top_cnt; sp++;
        // expand pooled means back to per-position y, clamp at 0
        int pos = 0;
        for (int b = 0; b < sp; b++) {
            float m   = st_sum[b] / (float)st_cnt[b];
            float val = fmaxf(m, 0.0f);
            int   c   = st_cnt[b];
            for (int q = 0; q < c; q++) yv[pos++] = val;
        }
    }
    __syncthreads();

    // ---- unsort + sign: z[perm[i]] = sign(x[perm[i]]) * y[i] ----
    {
        int   oi  = perm[tid];
        float sv  = sx[oi];
        float sgn = (sv > 0.0f) ? 1.0f : ((sv < 0.0f) ? -1.0f : 0.0f);
        zbuf[oi] = sgn * yv[tid];
    }
    __syncthreads();

    // ---- sparsemax: sort z descending (no payload) ----
    zs[tid] = zbuf[tid];
    __syncthreads();
    #pragma unroll 1
    for (int k = 2; k <= DD; k <<= 1) {
        #pragma unroll 1
        for (int j = k >> 1; j > 0; j >>= 1) {
            int ixj = tid ^ j;
            if (ixj > tid) {
                bool dec = ((tid & k) == 0);
                float a = zs[tid], b = zs[ixj];
                if ((a < b) == dec) { zs[tid] = b; zs[ixj] = a; }
            }
            __syncthreads();
        }
    }

    // ---- inclusive cumsum of zs (Hillis-Steele in st_sum) ----
    st_sum[tid] = zs[tid];
    __syncthreads();
    #pragma unroll 1
    for (int off = 1; off < DD; off <<= 1) {
        float t = st_sum[tid];
        if (tid >= off) t += st_sum[tid - off];
        __syncthreads();
        st_sum[tid] = t;
        __syncthreads();
    }

    // ---- support + tau ----
    bool flag = (1.0f + (float)(tid + 1) * zs[tid]) > st_sum[tid];
    int k_sup = __syncthreads_count(flag);   // support is a prefix -> count == k
    if (tid == 0) tau_sh = (st_sum[k_sup - 1] - 1.0f) / (float)k_sup;
    __syncthreads();

    out[row * DD + tid] = fmaxf(zbuf[tid] - tau_sh, 0.0f);
}

extern "C" void kernel_launch(void* const* d_in, const int* in_sizes, int n_in,
                              void* d_out, int out_size) {
    const float* x = (const float*)d_in[0];
    float* out = (float*)d_out;
    oscarmax_kernel<<<BB, DD>>>(x, out);
}

// round 2
// speedup vs baseline: 1.3868x; 1.3868x over previous
#include <cuda_runtime.h>

typedef unsigned long long u64;
typedef unsigned int u32;

#define DD 1024
#define BB 64
#define BETA_W 0.001f

__device__ __forceinline__ u64 ce_sel(u64 a, u64 b, bool takeMax) {
    return takeMax ? (a > b ? a : b) : (a < b ? a : b);
}

__global__ __launch_bounds__(1024) void oscarmax_kernel(const float* __restrict__ x,
                                                        float* __restrict__ out) {
    // 16KB sort buffer, reused after sort as 4 float/int arrays of 1024
    __shared__ u64 sbuf[2][DD];
    __shared__ float sgn_mark[DD];     // sign(x) first, then markerpos (int view)
    __shared__ float zcs[DD];          // zs (sorted z) then csum
    __shared__ int partials_i[32];
    __shared__ float partials_f[32];
    __shared__ int totalsh;

    float* fbase = (float*)sbuf;
    float* sy    = fbase;              // s values (isotonic input)
    float* ssum  = fbase + 1024;       // PAVA stack sums
    int*   scnt  = (int*)(fbase + 2048); // PAVA stack counts
    float* mval  = fbase + 3072;       // pool value at marker positions
    int*   markerpos = (int*)sgn_mark;

    const int tid  = threadIdx.x;
    const int lane = tid & 31;
    const int row  = blockIdx.x;

    // ---- load, compute sign, pack sortable u64 (key desc, idx asc tiebreak) ----
    float xv = x[row * DD + tid];
    sgn_mark[tid] = (xv > 0.0f) ? 1.0f : ((xv < 0.0f) ? -1.0f : 0.0f);
    u32 kb = __float_as_uint(fabsf(xv));     // nonneg float: uint order == float order
    u64 v = ((u64)kb << 32) | (u32)(~(u32)tid);

    // ---- bitonic sort, descending on packed u64 ----
    // Phase A: k = 2..32, all exchanges intra-warp via shfl (no barriers)
    #pragma unroll
    for (int k = 2; k <= 32; k <<= 1) {
        #pragma unroll
        for (int j = k >> 1; j > 0; j >>= 1) {
            u64 o = __shfl_xor_sync(0xffffffffu, v, j);
            bool lower = ((tid & j) == 0);
            bool dec   = ((tid & k) == 0);
            v = ce_sel(v, o, lower == dec);
        }
    }
    int cur = 0;
    sbuf[0][tid] = v;
    __syncthreads();

    // Phase B: k = 64..1024; cross-warp steps (j>=32) via double-buffered smem,
    // intra-warp tail (j<=16) via shfl.
    #pragma unroll 1
    for (int k = 64; k <= 1024; k <<= 1) {
        #pragma unroll 1
        for (int j = k >> 1; j >= 32; j >>= 1) {
            u64 o = sbuf[cur][tid ^ j];
            bool lower = ((tid & j) == 0);
            bool dec   = ((tid & k) == 0);
            v = ce_sel(v, o, lower == dec);
            sbuf[cur ^ 1][tid] = v;
            __syncthreads();
            cur ^= 1;
        }
        #pragma unroll
        for (int j = 16; j > 0; j >>= 1) {
            u64 o = __shfl_xor_sync(0xffffffffu, v, j);
            bool lower = ((tid & j) == 0);
            bool dec   = ((tid & k) == 0);
            v = ce_sel(v, o, lower == dec);
        }
        if (k < 1024) {                // last intra tail needs no smem publish
            sbuf[cur ^ 1][tid] = v;
            __syncthreads();
            cur ^= 1;
        }
    }

    // ---- unpack, gather sign (before sgn_mark is repurposed), write s ----
    float keyf  = __uint_as_float((u32)(v >> 32));
    int   idx   = (int)(~((u32)v));                 // original index (perm)
    float sgn_i = sgn_mark[idx];
    float s     = keyf - BETA_W * (float)(DD - 1 - tid);
    sy[tid] = s;                                    // aliases sort buffer (reads done)
    __syncthreads();

    markerpos[tid] = -1;                            // repurpose sgn_mark
    __syncthreads();

    // ---- PAVA (nonincreasing isotonic), serial on thread 0; marker output ----
    if (tid == 0) {
        int sp = 0;
        float top_sum = sy[0];
        float top_cnt = 1.0f;
        for (int i = 1; i < DD; i++) {
            float cs = sy[i];
            float cc = 1.0f;
            while (cs * top_cnt > top_sum * cc) {   // cur_mean > top_mean
                cs += top_sum; cc += top_cnt;
                if (sp > 0) { --sp; top_sum = ssum[sp]; top_cnt = (float)scnt[sp]; }
                else        { top_cnt = 0.0f; break; }
            }
            if (top_cnt > 0.0f) { ssum[sp] = top_sum; scnt[sp] = (int)top_cnt; sp++; }
            top_sum = cs; top_cnt = cc;
        }
        ssum[sp] = top_sum; scnt[sp] = (int)top_cnt; sp++;
        int pos = 0;
        for (int b = 0; b < sp; b++) {
            float val = fmaxf(ssum[b] / (float)scnt[b], 0.0f);
            mval[pos] = val;
            markerpos[pos] = pos;
            pos += scnt[b];
        }
    }
    __syncthreads();

    // ---- parallel fill-forward: block inclusive max-scan of markerpos ----
    int mp = markerpos[tid];
    #pragma unroll
    for (int o = 1; o < 32; o <<= 1) {
        int t = __shfl_up_sync(0xffffffffu, mp, o);
        if (lane >= o) mp = max(mp, t);
    }
    if (lane == 31) partials_i[tid >> 5] = mp;
    __syncthreads();
    if (tid < 32) {
        int p = partials_i[tid];
        #pragma unroll
        for (int o = 1; o < 32; o <<= 1) {
            int t = __shfl_up_sync(0xffffffffu, p, o);
            if (tid >= o) p = max(p, t);
        }
        partials_i[tid] = p;
    }
    __syncthreads();
    if (tid >= 32) mp = max(mp, partials_i[(tid >> 5) - 1]);

    float y = mval[mp];            // pooled mean, already clamped >= 0
    float z = sgn_i * y;           // oscar prox value at sorted position tid

    // ---- sorted-z construction without a sort: packed (P,N) rank scan ----
    __syncthreads();               // protect partials_i reuse
    int fP = (z > 0.0f) ? 1 : 0;
    int fN = (z < 0.0f) ? 1 : 0;
    int pk = (fP << 16) | fN;
    int incl = pk;
    #pragma unroll
    for (int o = 1; o < 32; o <<= 1) {
        int t = __shfl_up_sync(0xffffffffu, incl, o);
        if (lane >= o) incl += t;
    }
    if (lane == 31) partials_i[tid >> 5] = incl;
    __syncthreads();
    if (tid < 32) {
        int p = partials_i[tid];
        #pragma unroll
        for (int o = 1; o < 32; o <<= 1) {
            int t = __shfl_up_sync(0xffffffffu, p, o);
            if (tid >= o) p += t;
        }
        partials_i[tid] = p;
    }
    __syncthreads();
    if (tid >= 32) incl += partials_i[(tid >> 5) - 1];
    if (tid == DD - 1) totalsh = incl;
    int excl = incl - pk;
    __syncthreads();               // totalsh visible

    int pPex = excl >> 16;
    int pNex = excl & 0xffff;
    int totalP = totalsh >> 16;
    int pos;
    if (z > 0.0f)      pos = pPex;                                 // positives: i-order
    else if (z < 0.0f) pos = DD - 1 - pNex;                        // negatives: reverse i-order
    else               pos = totalP + (tid - pPex - pNex);         // zeros: middle
    zcs[pos] = z;
    __syncthreads();

    // ---- sparsemax: cumsum over sorted z, support count, tau ----
    float zs_t = zcs[tid];
    float c = zs_t;
    #pragma unroll
    for (int o = 1; o < 32; o <<= 1) {
        float t = __shfl_up_sync(0xffffffffu, c, o);
        if (lane >= o) c += t;
    }
    if (lane == 31) partials_f[tid >> 5] = c;
    __syncthreads();
    if (tid < 32) {
        float p = partials_f[tid];
        #pragma unroll
        for (int o = 1; o < 32; o <<= 1) {
            float t = __shfl_up_sync(0xffffffffu, p, o);
            if (tid >= o) p += t;
        }
        partials_f[tid] = p;
    }
    __syncthreads();
    if (tid >= 32) c += partials_f[(tid >> 5) - 1];

    zcs[tid] = c;                  // own slot; all zcs reads happened pre-scan
    bool flag = (1.0f + (float)(tid + 1) * zs_t) > c;
    int k_sup = __syncthreads_count(flag);       // support is a prefix; also a barrier
    float tau = (zcs[k_sup - 1] - 1.0f) / (float)k_sup;

    out[row * DD + idx] = fmaxf(z - tau, 0.0f);
}

extern "C" void kernel_launch(void* const* d_in, const int* in_sizes, int n_in,
                              void* d_out, int out_size) {
    const float* x = (const float*)d_in[0];
    float* out = (float*)d_out;
    oscarmax_kernel<<<BB, DD>>>(x, out);
}

// round 3
// speedup vs baseline: 2.9634x; 2.1368x over previous
#include <cuda_runtime.h>

typedef unsigned long long u64;
typedef unsigned int u32;

#define DD 1024
#define BB 64
#define BETA_W 0.001f

__device__ __forceinline__ u64 ce_sel(u64 a, u64 b, bool takeMax) {
    return takeMax ? (a > b ? a : b) : (a < b ? a : b);
}

__global__ __launch_bounds__(1024) void oscarmax_kernel(const float* __restrict__ x,
                                                        float* __restrict__ out) {
    __shared__ u64    sbuf[2][DD];     // bitonic sort double buffer (dead after sort)
    __shared__ float  sy[DD];          // s values (isotonic input)
    __shared__ float2 stk[DD + 2];     // PAVA stack: sentinel + up to D blocks
    __shared__ float  mval[DD];        // pool value at block-start positions
    __shared__ float  sgn_mark[DD];    // sign(x) first, then markerpos (int view)
    __shared__ float  zcs[DD];         // sorted z, then cumsum
    __shared__ int    partials_i[32];
    __shared__ float  partials_f[32];
    __shared__ int    totalsh;
    __shared__ int    spsh;

    int* markerpos = (int*)sgn_mark;

    const int tid  = threadIdx.x;
    const int lane = tid & 31;
    const int row  = blockIdx.x;

    // ---- load, sign, pack sortable u64 (|x| desc, idx asc tiebreak) ----
    float xv = x[row * DD + tid];
    sgn_mark[tid] = (xv > 0.0f) ? 1.0f : ((xv < 0.0f) ? -1.0f : 0.0f);
    u32 kb = __float_as_uint(fabsf(xv));
    u64 v = ((u64)kb << 32) | (u32)(~(u32)tid);

    // ---- bitonic sort (descending) ----
    #pragma unroll
    for (int k = 2; k <= 32; k <<= 1) {
        #pragma unroll
        for (int j = k >> 1; j > 0; j >>= 1) {
            u64 o = __shfl_xor_sync(0xffffffffu, v, j);
            bool lower = ((tid & j) == 0);
            bool dec   = ((tid & k) == 0);
            v = ce_sel(v, o, lower == dec);
        }
    }
    int cur = 0;
    sbuf[0][tid] = v;
    __syncthreads();
    #pragma unroll 1
    for (int k = 64; k <= 1024; k <<= 1) {
        #pragma unroll 1
        for (int j = k >> 1; j >= 32; j >>= 1) {
            u64 o = sbuf[cur][tid ^ j];
            bool lower = ((tid & j) == 0);
            bool dec   = ((tid & k) == 0);
            v = ce_sel(v, o, lower == dec);
            sbuf[cur ^ 1][tid] = v;
            __syncthreads();
            cur ^= 1;
        }
        #pragma unroll
        for (int j = 16; j > 0; j >>= 1) {
            u64 o = __shfl_xor_sync(0xffffffffu, v, j);
            bool lower = ((tid & j) == 0);
            bool dec   = ((tid & k) == 0);
            v = ce_sel(v, o, lower == dec);
        }
        if (k < 1024) {
            sbuf[cur ^ 1][tid] = v;
            __syncthreads();
            cur ^= 1;
        }
    }

    // ---- unpack, gather sign, write s ----
    float keyf  = __uint_as_float((u32)(v >> 32));
    int   idx   = (int)(~((u32)v));
    float sgn_i = sgn_mark[idx];
    sy[tid] = keyf - BETA_W * (float)(DD - 1 - tid);
    __syncthreads();

    // ---- PAVA serial on thread 0; other threads init markerpos ----
    markerpos[tid] = -1;
    if (tid == 0) {
        stk[0] = make_float2(1e30f, 1.0f);   // sentinel: never pools
        int sp = 1;
        float ts = sy[0], tc = 1.0f;
        float nv = sy[1];
        #pragma unroll 4
        for (int i = 1; i < DD; i++) {
            float cv = nv;
            nv = sy[(i + 1 < DD) ? (i + 1) : i];   // prefetch next, independent
            float cs = cv, cc = 1.0f;
            while (cs * tc > ts * cc) {            // cur_mean > top_mean
                cs += ts; cc += tc;
                --sp;
                float2 t = stk[sp];
                ts = t.x; tc = t.y;
            }
            stk[sp] = make_float2(ts, tc); sp++;
            ts = cs; tc = cc;
        }
        stk[sp] = make_float2(ts, tc); sp++;
        spsh = sp;
    }
    __syncthreads();

    // ---- parallel expansion: block starts via int prefix scan of counts ----
    int sp = spsh;
    int cnt = (tid >= 1 && tid < sp) ? (int)stk[tid].y : 0;
    int inc = cnt;
    #pragma unroll
    for (int o = 1; o < 32; o <<= 1) {
        int t = __shfl_up_sync(0xffffffffu, inc, o);
        if (lane >= o) inc += t;
    }
    if (lane == 31) partials_i[tid >> 5] = inc;
    __syncthreads();
    if (tid < 32) {
        int p = partials_i[tid];
        #pragma unroll
        for (int o = 1; o < 32; o <<= 1) {
            int t = __shfl_up_sync(0xffffffffu, p, o);
            if (tid >= o) p += t;
        }
        partials_i[tid] = p;
    }
    __syncthreads();
    if (tid >= 32) inc += partials_i[(tid >> 5) - 1];
    int start = inc - cnt;
    if (tid >= 1 && tid < sp) {
        mval[start] = fmaxf(stk[tid].x / stk[tid].y, 0.0f);
        markerpos[start] = start;
    }
    __syncthreads();

    // ---- fill-forward: block inclusive max-scan of markerpos ----
    int mp = markerpos[tid];
    #pragma unroll
    for (int o = 1; o < 32; o <<= 1) {
        int t = __shfl_up_sync(0xffffffffu, mp, o);
        if (lane >= o) mp = max(mp, t);
    }
    if (lane == 31) partials_i[tid >> 5] = mp;
    __syncthreads();
    if (tid < 32) {
        int p = partials_i[tid];
        #pragma unroll
        for (int o = 1; o < 32; o <<= 1) {
            int t = __shfl_up_sync(0xffffffffu, p, o);
            if (tid >= o) p = max(p, t);
        }
        partials_i[tid] = p;
    }
    __syncthreads();
    if (tid >= 32) mp = max(mp, partials_i[(tid >> 5) - 1]);

    float y = mval[mp];            // pooled mean, clamped >= 0, nonincreasing in tid
    float z = sgn_i * y;           // oscar prox at sorted position tid

    // ---- sorted-z without a sort: packed (P,N) rank scan ----
    __syncthreads();               // protect partials_i reuse
    int fP = (z > 0.0f) ? 1 : 0;
    int fN = (z < 0.0f) ? 1 : 0;
    int pk = (fP << 16) | fN;
    int incl = pk;
    #pragma unroll
    for (int o = 1; o < 32; o <<= 1) {
        int t = __shfl_up_sync(0xffffffffu, incl, o);
        if (lane >= o) incl += t;
    }
    if (lane == 31) partials_i[tid >> 5] = incl;
    __syncthreads();
    if (tid < 32) {
        int p = partials_i[tid];
        #pragma unroll
        for (int o = 1; o < 32; o <<= 1) {
            int t = __shfl_up_sync(0xffffffffu, p, o);
            if (tid >= o) p += t;
        }
        partials_i[tid] = p;
    }
    __syncthreads();
    if (tid >= 32) incl += partials_i[(tid >> 5) - 1];
    if (tid == DD - 1) totalsh = incl;
    int excl = incl - pk;
    __syncthreads();               // totalsh visible

    int pPex = excl >> 16;
    int pNex = excl & 0xffff;
    int totalP = totalsh >> 16;
    int pos;
    if (z > 0.0f)      pos = pPex;                          // positives: i-order
    else if (z < 0.0f) pos = DD - 1 - pNex;                 // negatives: reverse i-order
    else               pos = totalP + (tid - pPex - pNex);  // zeros: middle
    zcs[pos] = z;
    __syncthreads();

    // ---- sparsemax: cumsum, support count, tau ----
    float zs_t = zcs[tid];
    float c = zs_t;
    #pragma unroll
    for (int o = 1; o < 32; o <<= 1) {
        float t = __shfl_up_sync(0xffffffffu, c, o);
        if (lane >= o) c += t;
    }
    if (lane == 31) partials_f[tid >> 5] = c;
    __syncthreads();
    if (tid < 32) {
        float p = partials_f[tid];
        #pragma unroll
        for (int o = 1; o < 32; o <<= 1) {
            float t = __shfl_up_sync(0xffffffffu, p, o);
            if (tid >= o) p += t;
        }
        partials_f[tid] = p;
    }
    __syncthreads();
    if (tid >= 32) c += partials_f[(tid >> 5) - 1];

    zcs[tid] = c;
    bool flag = (1.0f + (float)(tid + 1) * zs_t) > c;
    int k_sup = __syncthreads_count(flag);   // support is a prefix; also a barrier
    float tau = (zcs[k_sup - 1] - 1.0f) / (float)k_sup;

    out[row * DD + idx] = fmaxf(z - tau, 0.0f);
}

extern "C" void kernel_launch(void* const* d_in, const int* in_sizes, int n_in,
                              void* d_out, int out_size) {
    const float* x = (const float*)d_in[0];
    float* out = (float*)d_out;
    oscarmax_kernel<<<BB, DD>>>(x, out);
}

// round 4
// speedup vs baseline: 3.0606x; 1.0328x over previous
#include <cuda_runtime.h>

typedef unsigned long long u64;
typedef unsigned int u32;

#define DD 1024
#define BB 64
#define BETA_W 0.001f

__device__ __forceinline__ u64 ce_sel(u64 a, u64 b, bool takeMax) {
    return takeMax ? (a > b ? a : b) : (a < b ? a : b);
}

__global__ __launch_bounds__(1024) void oscarmax_kernel(const float* __restrict__ x,
                                                        float* __restrict__ out) {
    __shared__ u64    sbuf[2][DD];     // sort double buffer; then (blist | chunk stacks)
    __shared__ float  sy[DD];          // s values (isotonic input)
    __shared__ float2 stkm[DD + 2];    // merge stack (sentinel + blocks)
    __shared__ float  mval[DD];        // pool value at block-start positions
    __shared__ float  sgn_mark[DD];    // sign(x) first, then markerpos (int view)
    __shared__ float  zcs[DD];         // sorted z, then cumsum
    __shared__ int    chunk_nb[32];
    __shared__ int    chunk_off[32];
    __shared__ int    partials_i[32];
    __shared__ float  partials_f[32];
    __shared__ int    totalsh;
    __shared__ int    spsh;
    __shared__ int    btot_sh;

    int* markerpos = (int*)sgn_mark;
    float2* blist = (float2*)sbuf;           // 1024 float2 (first 8KB of sbuf)
    float2* cstk  = ((float2*)sbuf) + 1024;  // 32 chunks x 32 blocks (second 8KB)

    const int tid  = threadIdx.x;
    const int lane = tid & 31;
    const int wrp  = tid >> 5;
    const int row  = blockIdx.x;

    // ---- load, sign, pack sortable u64 (|x| desc, idx asc tiebreak) ----
    float xv = x[row * DD + tid];
    sgn_mark[tid] = (xv > 0.0f) ? 1.0f : ((xv < 0.0f) ? -1.0f : 0.0f);
    u32 kb = __float_as_uint(fabsf(xv));
    u64 v = ((u64)kb << 32) | (u32)(~(u32)tid);

    // ---- bitonic sort (descending) ----
    #pragma unroll
    for (int k = 2; k <= 32; k <<= 1) {
        #pragma unroll
        for (int j = k >> 1; j > 0; j >>= 1) {
            u64 o = __shfl_xor_sync(0xffffffffu, v, j);
            bool lower = ((tid & j) == 0);
            bool dec   = ((tid & k) == 0);
            v = ce_sel(v, o, lower == dec);
        }
    }
    int cur = 0;
    sbuf[0][tid] = v;
    __syncthreads();
    #pragma unroll 1
    for (int k = 64; k <= 1024; k <<= 1) {
        #pragma unroll 1
        for (int j = k >> 1; j >= 32; j >>= 1) {
            u64 o = sbuf[cur][tid ^ j];
            bool lower = ((tid & j) == 0);
            bool dec   = ((tid & k) == 0);
            v = ce_sel(v, o, lower == dec);
            sbuf[cur ^ 1][tid] = v;
            __syncthreads();
            cur ^= 1;
        }
        #pragma unroll
        for (int j = 16; j > 0; j >>= 1) {
            u64 o = __shfl_xor_sync(0xffffffffu, v, j);
            bool lower = ((tid & j) == 0);
            bool dec   = ((tid & k) == 0);
            v = ce_sel(v, o, lower == dec);
        }
        if (k < 1024) {
            sbuf[cur ^ 1][tid] = v;
            __syncthreads();
            cur ^= 1;
        }
    }

    // ---- unpack, gather sign, write s ----
    float keyf  = __uint_as_float((u32)(v >> 32));
    int   idx   = (int)(~((u32)v));
    float sgn_i = sgn_mark[idx];
    sy[tid] = keyf - BETA_W * (float)(DD - 1 - tid);
    __syncthreads();   // sy ready; sbuf (sort data) dead -> reuse as blist/cstk

    // ---- level 1: per-chunk PAVA (32 chunks x 32 elems, lane 0 of each warp) ----
    if (lane == 0) {
        const int base = wrp * 32;
        float2* cb = cstk + base;
        int nb = 0;
        float ts = sy[base], tc = 1.0f;
        #pragma unroll 1
        for (int i = 1; i < 32; i++) {
            float cs = sy[base + i], cc = 1.0f;
            for (;;) {
                if (cs * tc > ts * cc) {          // violation: cur_mean > top_mean
                    cs += ts; cc += tc;
                    if (nb > 0) { --nb; ts = cb[nb].x; tc = cb[nb].y; }
                    else        { ts = cs; tc = cc; goto nexti; }
                } else break;
            }
            cb[nb++] = make_float2(ts, tc);
            ts = cs; tc = cc;
            nexti: ;
        }
        cb[nb++] = make_float2(ts, tc);
        chunk_nb[wrp] = nb;
    }
    __syncthreads();

    // ---- compaction offsets: exclusive scan of chunk_nb (warp 0) ----
    if (tid < 32) {
        int vq = chunk_nb[tid];
        int inc = vq;
        #pragma unroll
        for (int o = 1; o < 32; o <<= 1) {
            int t = __shfl_up_sync(0xffffffffu, inc, o);
            if (tid >= o) inc += t;
        }
        chunk_off[tid] = inc - vq;
        if (tid == 31) btot_sh = inc;
    }
    __syncthreads();

    // ---- parallel copy of chunk blocks into ordered blist ----
    if (lane < chunk_nb[wrp]) blist[chunk_off[wrp] + lane] = cstk[wrp * 32 + lane];
    markerpos[tid] = -1;    // init for expansion (sgn already consumed)
    __syncthreads();

    // ---- level 2: serial merge over blocks (thread 0), register TOS+second ----
    if (tid == 0) {
        const int btot = btot_sh;
        stkm[0] = make_float2(1e30f, 1.0f);     // sentinel
        int d = 1;
        float ts = blist[0].x, tc = blist[0].y; // top = S[d]
        float ss = 1e30f, sc = 1.0f;            // second = S[d-1]
        float2 nx = blist[1];
        #pragma unroll 1
        for (int i = 1; i < btot; ) {
            float2 nnx = blist[(i + 1 < btot) ? (i + 1) : i];   // prefetch
            while (nx.x * tc > ts * nx.y) {     // pop & absorb
                nx.x += ts; nx.y += tc;
                --d;
                ts = ss; tc = sc;
                float2 dd = stkm[d - 1];
                ss = dd.x; sc = dd.y;
            }
            stkm[d - 1] = make_float2(ss, sc);  // push
            ss = ts; sc = tc;
            ts = nx.x; tc = nx.y;
            ++d;
            ++i;
            nx = nnx;
        }
        stkm[d - 1] = make_float2(ss, sc);
        stkm[d]     = make_float2(ts, tc);
        spsh = d;                                // final blocks = stkm[1..d]
    }
    __syncthreads();

    // ---- parallel expansion: block starts via int prefix scan of counts ----
    int d = spsh;
    int cnt = (tid < d) ? (int)stkm[tid + 1].y : 0;
    int inc = cnt;
    #pragma unroll
    for (int o = 1; o < 32; o <<= 1) {
        int t = __shfl_up_sync(0xffffffffu, inc, o);
        if (lane >= o) inc += t;
    }
    if (lane == 31) partials_i[wrp] = inc;
    __syncthreads();
    if (tid < 32) {
        int p = partials_i[tid];
        #pragma unroll
        for (int o = 1; o < 32; o <<= 1) {
            int t = __shfl_up_sync(0xffffffffu, p, o);
            if (tid >= o) p += t;
        }
        partials_i[tid] = p;
    }
    __syncthreads();
    if (tid >= 32) inc += partials_i[wrp - 1];
    int start = inc - cnt;
    if (tid < d) {
        mval[start] = fmaxf(stkm[tid + 1].x / stkm[tid + 1].y, 0.0f);
        markerpos[start] = start;
    }
    __syncthreads();

    // ---- fill-forward: block inclusive max-scan of markerpos ----
    int mp = markerpos[tid];
    #pragma unroll
    for (int o = 1; o < 32; o <<= 1) {
        int t = __shfl_up_sync(0xffffffffu, mp, o);
        if (lane >= o) mp = max(mp, t);
    }
    if (lane == 31) partials_i[wrp] = mp;
    __syncthreads();
    if (tid < 32) {
        int p = partials_i[tid];
        #pragma unroll
        for (int o = 1; o < 32; o <<= 1) {
            int t = __shfl_up_sync(0xffffffffu, p, o);
            if (tid >= o) p = max(p, t);
        }
        partials_i[tid] = p;
    }
    __syncthreads();
    if (tid >= 32) mp = max(mp, partials_i[wrp - 1]);

    float y = mval[mp];            // pooled mean, clamped >= 0, nonincreasing in tid
    float z = sgn_i * y;           // oscar prox at sorted position tid

    // ---- sorted-z without a sort: packed (P,N) rank scan ----
    __syncthreads();               // protect partials_i reuse
    int fP = (z > 0.0f) ? 1 : 0;
    int fN = (z < 0.0f) ? 1 : 0;
    int pk = (fP << 16) | fN;
    int incl = pk;
    #pragma unroll
    for (int o = 1; o < 32; o <<= 1) {
        int t = __shfl_up_sync(0xffffffffu, incl, o);
        if (lane >= o) incl += t;
    }
    if (lane == 31) partials_i[wrp] = incl;
    __syncthreads();
    if (tid < 32) {
        int p = partials_i[tid];
        #pragma unroll
        for (int o = 1; o < 32; o <<= 1) {
            int t = __shfl_up_sync(0xffffffffu, p, o);
            if (tid >= o) p += t;
        }
        partials_i[tid] = p;
    }
    __syncthreads();
    if (tid >= 32) incl += partials_i[wrp - 1];
    if (tid == DD - 1) totalsh = incl;
    int excl = incl - pk;
    __syncthreads();               // totalsh visible

    int pPex = excl >> 16;
    int pNex = excl & 0xffff;
    int totalP = totalsh >> 16;
    int pos;
    if (z > 0.0f)      pos = pPex;                          // positives: i-order
    else if (z < 0.0f) pos = DD - 1 - pNex;                 // negatives: reverse i-order
    else               pos = totalP + (tid - pPex - pNex);  // zeros: middle
    zcs[pos] = z;
    __syncthreads();

    // ---- sparsemax: cumsum, support count, tau ----
    float zs_t = zcs[tid];
    float c = zs_t;
    #pragma unroll
    for (int o = 1; o < 32; o <<= 1) {
        float t = __shfl_up_sync(0xffffffffu, c, o);
        if (lane >= o) c += t;
    }
    if (lane == 31) partials_f[wrp] = c;
    __syncthreads();
    if (tid < 32) {
        float p = partials_f[tid];
        #pragma unroll
        for (int o = 1; o < 32; o <<= 1) {
            float t = __shfl_up_sync(0xffffffffu, p, o);
            if (tid >= o) p += t;
        }
        partials_f[tid] = p;
    }
    __syncthreads();
    if (tid >= 32) c += partials_f[wrp - 1];

    zcs[tid] = c;
    bool flag = (1.0f + (float)(tid + 1) * zs_t) > c;
    int k_sup = __syncthreads_count(flag);   // support is a prefix; also a barrier
    float tau = (zcs[k_sup - 1] - 1.0f) / (float)k_sup;

    out[row * DD + idx] = fmaxf(z - tau, 0.0f);
}

extern "C" void kernel_launch(void* const* d_in, const int* in_sizes, int n_in,
                              void* d_out, int out_size) {
    const float* x = (const float*)d_in[0];
    float* out = (float*)d_out;
    oscarmax_kernel<<<BB, DD>>>(x, out);
}

// round 5
// speedup vs baseline: 7.8057x; 2.5504x over previous
#include <cuda_runtime.h>

typedef unsigned long long u64;
typedef unsigned int u32;

#define DD 1024
#define BB 64
#define BETA_W 0.001f

__device__ __forceinline__ u64 ce_sel(u64 a, u64 b, bool takeMax) {
    return takeMax ? (a > b ? a : b) : (a < b ? a : b);
}

// Merge two adjacent isotonic block ranges in-place.
// Blocks: float2 {sum, cnt}; invalid slot => cnt == 0. Ranges are contiguous valid slots.
__device__ __forceinline__ void cascade_merge(float2* b, int ls, int le, int rs, int re) {
    float2 L = b[le - 1];
    float2 P = b[rs];
    if (L.x * P.y < P.x * L.y) {           // left tail mean < right head mean: violation
        P.x += L.x; P.y += L.y;
        b[le - 1].y = 0.0f;
        b[rs].y = 0.0f;
        int li = le - 2;
        int ri = rs + 1;
        bool changed = true;
        while (changed) {
            changed = false;
            while (li >= ls) {
                float2 Lb = b[li];
                if (Lb.x * P.y < P.x * Lb.y) {
                    P.x += Lb.x; P.y += Lb.y; b[li].y = 0.0f; --li; changed = true;
                } else break;
            }
            while (ri < re) {
                float2 Rb = b[ri];
                if (Rb.x * P.y > P.x * Rb.y) {
                    P.x += Rb.x; P.y += Rb.y; b[ri].y = 0.0f; ++ri; changed = true;
                } else break;
            }
        }
        b[li + 1] = P;                      // pooled block at its sequence position
    }
}

__device__ __forceinline__ int block_scan_add(int v, int tid, int lane, int wrp, int* partials) {
    __syncthreads();                        // protect partials reuse
    int inc = v;
    #pragma unroll
    for (int o = 1; o < 32; o <<= 1) {
        int t = __shfl_up_sync(0xffffffffu, inc, o);
        if (lane >= o) inc += t;
    }
    if (lane == 31) partials[wrp] = inc;
    __syncthreads();
    if (tid < 32) {
        int p = partials[tid];
        #pragma unroll
        for (int o = 1; o < 32; o <<= 1) {
            int t = __shfl_up_sync(0xffffffffu, p, o);
            if (tid >= o) p += t;
        }
        partials[tid] = p;
    }
    __syncthreads();
    if (wrp > 0) inc += partials[wrp - 1];
    return inc;
}

__global__ __launch_bounds__(1024) void oscarmax_kernel(const float* __restrict__ x,
                                                        float* __restrict__ out) {
    __shared__ u64   sbuf[2][DD];      // sort double buffer; then 2x 1024 float2 block buffers
    __shared__ float sy[DD];           // s values; later int view = exclusive scan (scanex)
    __shared__ float mval[DD];         // pool value at block-start positions
    __shared__ float sgn_mark[DD];     // sign(x); then markerpos (int view)
    __shared__ float zcs[DD];          // sorted z, then cumsum
    __shared__ int   chunk_nb[32];
    __shared__ int   seg_start[33];
    __shared__ int   partials_i[32];
    __shared__ float partials_f[32];
    __shared__ int   totalsh;

    int*    markerpos = (int*)sgn_mark;
    int*    scanex    = (int*)sy;
    float2* bA = (float2*)sbuf;
    float2* bB = ((float2*)sbuf) + DD;

    const int tid  = threadIdx.x;
    const int lane = tid & 31;
    const int wrp  = tid >> 5;
    const int row  = blockIdx.x;

    // ---- load, sign, pack sortable u64 (|x| desc, idx asc tiebreak) ----
    float xv = x[row * DD + tid];
    sgn_mark[tid] = (xv > 0.0f) ? 1.0f : ((xv < 0.0f) ? -1.0f : 0.0f);
    u32 kb = __float_as_uint(fabsf(xv));
    u64 v = ((u64)kb << 32) | (u32)(~(u32)tid);

    // ---- bitonic sort (descending) ----
    #pragma unroll
    for (int k = 2; k <= 32; k <<= 1) {
        #pragma unroll
        for (int j = k >> 1; j > 0; j >>= 1) {
            u64 o = __shfl_xor_sync(0xffffffffu, v, j);
            bool lower = ((tid & j) == 0);
            bool dec   = ((tid & k) == 0);
            v = ce_sel(v, o, lower == dec);
        }
    }
    int cur = 0;
    sbuf[0][tid] = v;
    __syncthreads();
    #pragma unroll 1
    for (int k = 64; k <= 1024; k <<= 1) {
        #pragma unroll 1
        for (int j = k >> 1; j >= 32; j >>= 1) {
            u64 o = sbuf[cur][tid ^ j];
            bool lower = ((tid & j) == 0);
            bool dec   = ((tid & k) == 0);
            v = ce_sel(v, o, lower == dec);
            sbuf[cur ^ 1][tid] = v;
            __syncthreads();
            cur ^= 1;
        }
        #pragma unroll
        for (int j = 16; j > 0; j >>= 1) {
            u64 o = __shfl_xor_sync(0xffffffffu, v, j);
            bool lower = ((tid & j) == 0);
            bool dec   = ((tid & k) == 0);
            v = ce_sel(v, o, lower == dec);
        }
        if (k < 1024) {
            sbuf[cur ^ 1][tid] = v;
            __syncthreads();
            cur ^= 1;
        }
    }

    // ---- unpack, gather sign, write s ----
    float keyf  = __uint_as_float((u32)(v >> 32));
    int   idx   = (int)(~((u32)v));
    float sgn_i = sgn_mark[idx];
    sy[tid] = keyf - BETA_W * (float)(DD - 1 - tid);
    __syncthreads();     // sy ready; sort buffer dead -> block buffers

    // ---- level 1: per-chunk PAVA (32 chunks x 32 elems), stack = bA slots ----
    if (lane == 0) {
        const int base = wrp << 5;
        float2* cb = bA + base;
        int nb = 0;
        float ts = sy[base], tc = 1.0f;
        #pragma unroll 1
        for (int i = 1; i < 32; i++) {
            float cs = sy[base + i], cc = 1.0f;
            for (;;) {
                if (cs * tc > ts * cc) {
                    cs += ts; cc += tc;
                    if (nb > 0) { --nb; ts = cb[nb].x; tc = cb[nb].y; }
                    else        { ts = cs; tc = cc; goto nexti; }
                } else break;
            }
            cb[nb++] = make_float2(ts, tc);
            ts = cs; tc = cc;
            nexti: ;
        }
        cb[nb++] = make_float2(ts, tc);
        chunk_nb[wrp] = nb;
    }
    __syncthreads();

    // invalidate unused chunk slots; init markers; init seg metadata
    if (lane >= chunk_nb[wrp]) bA[(wrp << 5) + lane] = make_float2(0.0f, 0.0f);
    markerpos[tid] = -1;
    if (tid <= 32) seg_start[tid] = tid << 5;
    __syncthreads();

    // ---- level 0 merge: 16 chunk-pair junction cascades (contiguous chunk blocks) ----
    if (lane == 0 && wrp < 16) {
        int c0 = wrp * 2, c1 = c0 + 1;
        cascade_merge(bA, c0 << 5, (c0 << 5) + chunk_nb[c0],
                          c1 << 5, (c1 << 5) + chunk_nb[c1]);
    }
    __syncthreads();

    // ---- merge tree: 4x (compact + pair metadata + junction cascade) ----
    float2* cu = bA;
    float2* ot = bB;
    int nseg = 32;
    int nslots = DD;
    #pragma unroll 1
    for (int lvl = 0; lvl < 4; lvl++) {
        // compact cu -> ot
        float2 bv = make_float2(0.0f, 0.0f);
        int flag = 0;
        if (tid < nslots) { bv = cu[tid]; flag = (bv.y > 0.0f) ? 1 : 0; }
        int inc = block_scan_add(flag, tid, lane, wrp, partials_i);
        scanex[tid] = inc - flag;
        if (flag) ot[inc - 1] = bv;
        if (tid == nslots - 1) totalsh = inc;
        __syncthreads();
        // pair metadata: nseg -> nseg/2
        int halfseg = nseg >> 1;
        int nsv = 0;
        if (tid < halfseg) nsv = scanex[seg_start[2 * tid]];
        int ntot = totalsh;
        __syncthreads();
        if (tid < halfseg)  seg_start[tid] = nsv;
        if (tid == halfseg) seg_start[tid] = ntot;
        nslots = ntot;
        nseg = halfseg;
        __syncthreads();
        // junction cascades on the new segments (pairs of them)
        if (lane == 0 && wrp < (nseg >> 1)) {
            int u = wrp;
            cascade_merge(ot, seg_start[2 * u],     seg_start[2 * u + 1],
                              seg_start[2 * u + 1], seg_start[2 * u + 2]);
        }
        __syncthreads();
        float2* tmp = cu; cu = ot; ot = tmp;
    }
    // final blocks in cu, slots [0, nslots) with gaps (cnt==0)

    // ---- parallel expansion: block starts via prefix scan of counts ----
    float2 bfin = make_float2(0.0f, 0.0f);
    int cnt = 0;
    if (tid < nslots) { bfin = cu[tid]; cnt = (int)bfin.y; }
    int incc = block_scan_add(cnt, tid, lane, wrp, partials_i);
    int start = incc - cnt;
    if (cnt > 0) {
        mval[start] = fmaxf(bfin.x / bfin.y, 0.0f);
        markerpos[start] = start;
    }
    __syncthreads();

    // ---- fill-forward: block inclusive max-scan of markerpos ----
    int mp = markerpos[tid];
    #pragma unroll
    for (int o = 1; o < 32; o <<= 1) {
        int t = __shfl_up_sync(0xffffffffu, mp, o);
        if (lane >= o) mp = max(mp, t);
    }
    if (lane == 31) partials_i[wrp] = mp;
    __syncthreads();
    if (tid < 32) {
        int p = partials_i[tid];
        #pragma unroll
        for (int o = 1; o < 32; o <<= 1) {
            int t = __shfl_up_sync(0xffffffffu, p, o);
            if (tid >= o) p = max(p, t);
        }
        partials_i[tid] = p;
    }
    __syncthreads();
    if (wrp > 0) mp = max(mp, partials_i[wrp - 1]);

    float y = mval[mp];            // pooled mean, clamped >= 0, nonincreasing in tid
    float z = sgn_i * y;           // oscar prox at sorted position tid

    // ---- sorted-z without a sort: packed (P,N) rank scan ----
    int fP = (z > 0.0f) ? 1 : 0;
    int fN = (z < 0.0f) ? 1 : 0;
    int pk = (fP << 16) | fN;
    int incl = block_scan_add(pk, tid, lane, wrp, partials_i);
    if (tid == DD - 1) totalsh = incl;
    int excl = incl - pk;
    __syncthreads();               // totalsh visible

    int pPex = excl >> 16;
    int pNex = excl & 0xffff;
    int totalP = totalsh >> 16;
    int pos;
    if (z > 0.0f)      pos = pPex;                          // positives: i-order
    else if (z < 0.0f) pos = DD - 1 - pNex;                 // negatives: reverse i-order
    else               pos = totalP + (tid - pPex - pNex);  // zeros: middle
    zcs[pos] = z;
    __syncthreads();

    // ---- sparsemax: cumsum, support count, tau ----
    float zs_t = zcs[tid];
    float c = zs_t;
    #pragma unroll
    for (int o = 1; o < 32; o <<= 1) {
        float t = __shfl_up_sync(0xffffffffu, c, o);
        if (lane >= o) c += t;
    }
    if (lane == 31) partials_f[wrp] = c;
    __syncthreads();
    if (tid < 32) {
        float p = partials_f[tid];
        #pragma unroll
        for (int o = 1; o < 32; o <<= 1) {
            float t = __shfl_up_sync(0xffffffffu, p, o);
            if (tid >= o) p += t;
        }
        partials_f[tid] = p;
    }
    __syncthreads();
    if (wrp > 0) c += partials_f[wrp - 1];

    zcs[tid] = c;
    bool flagS = (1.0f + (float)(tid + 1) * zs_t) > c;
    int k_sup = __syncthreads_count(flagS);   // support is a prefix; also a barrier
    float tau = (zcs[k_sup - 1] - 1.0f) / (float)k_sup;

    out[row * DD + idx] = fmaxf(z - tau, 0.0f);
}

extern "C" void kernel_launch(void* const* d_in, const int* in_sizes, int n_in,
                              void* d_out, int out_size) {
    const float* x = (const float*)d_in[0];
    float* out = (float*)d_out;
    oscarmax_kernel<<<BB, DD>>>(x, out);
}